// round 14
// baseline (speedup 1.0000x reference)
#include <cuda_runtime.h>
#include <cuda_bf16.h>

// x = (N=2, C=16, D=96, H=128, W=128) fp32; out = concat(gx, gy, gz).
// R5/R13 body (register z-rings, 1-plane register prefetch, shuffle x-halo)
// + atomic work-stealing over 1024 (y, z-half, nc) tiles from a persistent
// 592-CTA grid. Counters self-reset (last CTA out), so graph replays are
// deterministic with no host-side writes.

#define W_   128
#define H_   128
#define D_   96
#define NC_  32
#define YT_  8
#define ZC_  48
#define HW_  (H_ * W_)
#define CST_ (D_ * HW_)
#define V_   (NC_ * CST_)
#define TILES_Y 16               // H/YT
#define TILES_Z 2                // D/ZC
#define NTILES  (TILES_Y * TILES_Z * NC_)   // 1024
#define GRID_   592              // 148 SMs * 4 resident CTAs

__device__ unsigned int g_ticket = 0;
__device__ unsigned int g_done   = 0;

__device__ __forceinline__ float4 ld4z(const float* p, bool ok) {
    if (ok) return *reinterpret_cast<const float4*>(p);
    return make_float4(0.f, 0.f, 0.f, 0.f);
}

__global__ __launch_bounds__(256, 4)
void sobel3d_kernel(const float* __restrict__ in, float* __restrict__ out) {
    __shared__ unsigned int s_tile;

    const int lane = threadIdx.x;            // 0..31
    const int ty   = threadIdx.y;            // 0..7
    const bool t0  = (lane == 0) && (ty == 0);
    const int x4   = lane * 4;

    float* gx = out;
    float* gy = out + V_;
    float* gz = out + 2 * V_;

    for (;;) {
        if (t0) s_tile = atomicAdd(&g_ticket, 1u);
        __syncthreads();
        const unsigned int tile = s_tile;
        __syncthreads();
        if (tile >= NTILES) break;

        const int yt = tile & (TILES_Y - 1);
        const int zt = (tile >> 4) & (TILES_Z - 1);
        const int nc = tile >> 5;

        const int y  = yt * YT_ + ty;
        const int z0 = zt * ZC_;

        const float* src = in + nc * CST_;
        const bool ym_ok = (y > 0);
        const bool yp_ok = (y < H_ - 1);
        const int rm_off = (y - 1) * W_ + x4;
        const int r0_off = y * W_ + x4;
        const int rp_off = (y + 1) * W_ + x4;
        const int obase  = nc * CST_ + y * W_ + x4;

        float4 zz = make_float4(0.f, 0.f, 0.f, 0.f);
        float4 s_m = zz, s_0 = zz, d_m = zz, d_0 = zz;

        // prefetch plane z0-1 (zero if out of range)
        float4 f_m, f_0, f_p;
        {
            const int pz = z0 - 1;
            const bool zin = (pz >= 0);
            const float* pl = src + pz * HW_;
            f_m = ld4z(pl + rm_off, zin && ym_ok);
            f_0 = ld4z(pl + r0_off, zin);
            f_p = ld4z(pl + rp_off, zin && yp_ok);
        }

        #pragma unroll 3
        for (int i = 0; i < ZC_ + 2; ++i) {
            const int pz = z0 - 1 + i;

            float4 s_p, d_p;
            d_p.x = f_p.x - f_m.x; d_p.y = f_p.y - f_m.y;
            d_p.z = f_p.z - f_m.z; d_p.w = f_p.w - f_m.w;
            s_p.x = f_m.x + 2.f * f_0.x + f_p.x;
            s_p.y = f_m.y + 2.f * f_0.y + f_p.y;
            s_p.z = f_m.z + 2.f * f_0.z + f_p.z;
            s_p.w = f_m.w + 2.f * f_0.w + f_p.w;

            if (i < ZC_ + 1) {
                const int nz = pz + 1;                  // z0+i, always >= 0
                const bool zin = (nz < D_);
                const float* pl = src + nz * HW_;
                f_m = ld4z(pl + rm_off, zin && ym_ok);
                f_0 = ld4z(pl + r0_off, zin);
                f_p = ld4z(pl + rp_off, zin && yp_ok);
            }

            if (i >= 2) {
                float4 Sz, Dz, Zc;
                Sz.x = s_m.x + 2.f * s_0.x + s_p.x;
                Sz.y = s_m.y + 2.f * s_0.y + s_p.y;
                Sz.z = s_m.z + 2.f * s_0.z + s_p.z;
                Sz.w = s_m.w + 2.f * s_0.w + s_p.w;
                Dz.x = d_m.x + 2.f * d_0.x + d_p.x;
                Dz.y = d_m.y + 2.f * d_0.y + d_p.y;
                Dz.z = d_m.z + 2.f * d_0.z + d_p.z;
                Dz.w = d_m.w + 2.f * d_0.w + d_p.w;
                Zc.x = s_p.x - s_m.x; Zc.y = s_p.y - s_m.y;
                Zc.z = s_p.z - s_m.z; Zc.w = s_p.w - s_m.w;

                float SzL = __shfl_up_sync(0xffffffffu, Sz.w, 1);
                float SzR = __shfl_down_sync(0xffffffffu, Sz.x, 1);
                float DzL = __shfl_up_sync(0xffffffffu, Dz.w, 1);
                float DzR = __shfl_down_sync(0xffffffffu, Dz.x, 1);
                float ZcL = __shfl_up_sync(0xffffffffu, Zc.w, 1);
                float ZcR = __shfl_down_sync(0xffffffffu, Zc.x, 1);
                if (lane == 0)  { SzL = 0.f; DzL = 0.f; ZcL = 0.f; }
                if (lane == 31) { SzR = 0.f; DzR = 0.f; ZcR = 0.f; }

                float4 vx, vy, vz;
                vx.x = Sz.y - SzL;  vx.y = Sz.z - Sz.x;
                vx.z = Sz.w - Sz.y; vx.w = SzR  - Sz.z;
                vy.x = DzL  + 2.f * Dz.x + Dz.y;
                vy.y = Dz.x + 2.f * Dz.y + Dz.z;
                vy.z = Dz.y + 2.f * Dz.z + Dz.w;
                vy.w = Dz.z + 2.f * Dz.w + DzR;
                vz.x = ZcL  + 2.f * Zc.x + Zc.y;
                vz.y = Zc.x + 2.f * Zc.y + Zc.z;
                vz.z = Zc.y + 2.f * Zc.z + Zc.w;
                vz.w = Zc.z + 2.f * Zc.w + ZcR;

                const int o = obase + (pz - 1) * HW_;
                __stcs(reinterpret_cast<float4*>(gx + o), vx);
                __stcs(reinterpret_cast<float4*>(gy + o), vy);
                __stcs(reinterpret_cast<float4*>(gz + o), vz);
            }
            s_m = s_0; s_0 = s_p;
            d_m = d_0; d_0 = d_p;
        }
    }

    // Self-reset: the last CTA to exit restores the counters so the next
    // graph replay starts from ticket 0. Stream ordering guarantees no
    // overlap with the next launch.
    if (t0) {
        __threadfence();
        unsigned int d = atomicAdd(&g_done, 1u);
        if (d == GRID_ - 1) {
            atomicExch(&g_ticket, 0u);
            __threadfence();
            atomicExch(&g_done, 0u);
        }
    }
}

extern "C" void kernel_launch(void* const* d_in, const int* in_sizes, int n_in,
                              void* d_out, int out_size) {
    const float* x = (const float*)d_in[0];
    float* out = (float*)d_out;

    dim3 block(32, YT_, 1);        // 256 threads
    dim3 grid(GRID_, 1, 1);        // 148 SMs x 4 CTAs, work-stealing
    sobel3d_kernel<<<grid, block>>>(x, out);
}

// round 15
// speedup vs baseline: 1.0193x; 1.0193x over previous
#include <cuda_runtime.h>
#include <cuda_bf16.h>

// x = (N=2, C=16, D=96, H=128, W=128) fp32; out = concat(gx, gy, gz).
// R13 kernel with default write-back stores instead of __stcs:
// register z-rings of y-convolutions, 1-plane register prefetch,
// shuffle x-halo, one wave of 512 CTAs, unroll 3.

#define W_   128
#define H_   128
#define D_   96
#define NC_  32
#define YT_  8
#define HW_  (H_ * W_)          // 16384
#define CST_ (D_ * HW_)         // per-nc stride
#define V_   (NC_ * CST_)       // per-output-tensor elements

__device__ __forceinline__ float4 ld4z(const float* p, bool ok) {
    if (ok) return *reinterpret_cast<const float4*>(p);
    return make_float4(0.f, 0.f, 0.f, 0.f);
}

__global__ __launch_bounds__(256, 4)
void sobel3d_kernel(const float* __restrict__ in, float* __restrict__ out) {
    const int lane = threadIdx.x;                    // 0..31
    const int y    = blockIdx.x * YT_ + threadIdx.y; // 0..127
    const int nc   = blockIdx.y;                     // 0..31
    const int x4   = lane * 4;

    const float* src = in + nc * CST_;
    float* gx = out;
    float* gy = out + V_;
    float* gz = out + 2 * V_;

    const bool ym_ok = (y > 0);
    const bool yp_ok = (y < H_ - 1);
    const int rm_off = (y - 1) * W_ + x4;
    const int r0_off = y * W_ + x4;
    const int rp_off = (y + 1) * W_ + x4;
    const int obase  = nc * CST_ + y * W_ + x4;

    // z rings of per-plane y-convolutions: s = smooth_y, d = deriv_y
    float4 zz = make_float4(0.f, 0.f, 0.f, 0.f);
    float4 s_m = zz, s_0 = zz, d_m = zz, d_0 = zz;

    // prefetch plane 0
    float4 f_m = ld4z(src + rm_off, ym_ok);
    float4 f_0 = *reinterpret_cast<const float4*>(src + r0_off);
    float4 f_p = ld4z(src + rp_off, yp_ok);

    #pragma unroll 3
    for (int pz = 0; pz <= D_; ++pz) {
        // consume prefetched plane into s/d (frees f_* immediately)
        float4 s_p, d_p;
        d_p.x = f_p.x - f_m.x; d_p.y = f_p.y - f_m.y;
        d_p.z = f_p.z - f_m.z; d_p.w = f_p.w - f_m.w;
        s_p.x = f_m.x + 2.f * f_0.x + f_p.x;
        s_p.y = f_m.y + 2.f * f_0.y + f_p.y;
        s_p.z = f_m.z + 2.f * f_0.z + f_p.z;
        s_p.w = f_m.w + 2.f * f_0.w + f_p.w;

        // issue next plane's loads before the shuffle/store chain
        if (pz < D_) {
            const bool zin = (pz + 1) < D_;
            const float* pl = src + (pz + 1) * HW_;
            f_m = ld4z(pl + rm_off, zin && ym_ok);
            f_0 = ld4z(pl + r0_off, zin);
            f_p = ld4z(pl + rp_off, zin && yp_ok);
        }

        if (pz >= 1) {
            // z-combine first, then x-convolve the combined values
            float4 Sz, Dz, Zc;
            Sz.x = s_m.x + 2.f * s_0.x + s_p.x;
            Sz.y = s_m.y + 2.f * s_0.y + s_p.y;
            Sz.z = s_m.z + 2.f * s_0.z + s_p.z;
            Sz.w = s_m.w + 2.f * s_0.w + s_p.w;
            Dz.x = d_m.x + 2.f * d_0.x + d_p.x;
            Dz.y = d_m.y + 2.f * d_0.y + d_p.y;
            Dz.z = d_m.z + 2.f * d_0.z + d_p.z;
            Dz.w = d_m.w + 2.f * d_0.w + d_p.w;
            Zc.x = s_p.x - s_m.x; Zc.y = s_p.y - s_m.y;
            Zc.z = s_p.z - s_m.z; Zc.w = s_p.w - s_m.w;

            float SzL = __shfl_up_sync(0xffffffffu, Sz.w, 1);
            float SzR = __shfl_down_sync(0xffffffffu, Sz.x, 1);
            float DzL = __shfl_up_sync(0xffffffffu, Dz.w, 1);
            float DzR = __shfl_down_sync(0xffffffffu, Dz.x, 1);
            float ZcL = __shfl_up_sync(0xffffffffu, Zc.w, 1);
            float ZcR = __shfl_down_sync(0xffffffffu, Zc.x, 1);
            if (lane == 0)  { SzL = 0.f; DzL = 0.f; ZcL = 0.f; }
            if (lane == 31) { SzR = 0.f; DzR = 0.f; ZcR = 0.f; }

            float4 vx, vy, vz;
            vx.x = Sz.y - SzL;  vx.y = Sz.z - Sz.x;
            vx.z = Sz.w - Sz.y; vx.w = SzR  - Sz.z;
            vy.x = DzL  + 2.f * Dz.x + Dz.y;
            vy.y = Dz.x + 2.f * Dz.y + Dz.z;
            vy.z = Dz.y + 2.f * Dz.z + Dz.w;
            vy.w = Dz.z + 2.f * Dz.w + DzR;
            vz.x = ZcL  + 2.f * Zc.x + Zc.y;
            vz.y = Zc.x + 2.f * Zc.y + Zc.z;
            vz.z = Zc.y + 2.f * Zc.z + Zc.w;
            vz.w = Zc.z + 2.f * Zc.w + ZcR;

            const int o = obase + (pz - 1) * HW_;
            *reinterpret_cast<float4*>(gx + o) = vx;
            *reinterpret_cast<float4*>(gy + o) = vy;
            *reinterpret_cast<float4*>(gz + o) = vz;
        }
        s_m = s_0; s_0 = s_p;
        d_m = d_0; d_0 = d_p;
    }
}

extern "C" void kernel_launch(void* const* d_in, const int* in_sizes, int n_in,
                              void* d_out, int out_size) {
    const float* x = (const float*)d_in[0];
    float* out = (float*)d_out;

    dim3 block(32, YT_, 1);            // 256 threads
    dim3 grid(H_ / YT_, NC_, 1);       // 512 blocks, one wave
    sobel3d_kernel<<<grid, block>>>(x, out);
}

// round 16
// speedup vs baseline: 1.0435x; 1.0238x over previous
#include <cuda_runtime.h>
#include <cuda_bf16.h>

// x = (N=2, C=16, D=96, H=128, W=128) fp32; out = concat(gx, gy, gz).
// R13 kernel + __ldcs streaming loads (evict-first) so L2 capacity goes to
// write-burst buffering: register z-rings of y-convolutions, 1-plane register
// prefetch, shuffle x-halo, one wave of 512 CTAs, unroll 3, __stcs stores.

#define W_   128
#define H_   128
#define D_   96
#define NC_  32
#define YT_  8
#define HW_  (H_ * W_)          // 16384
#define CST_ (D_ * HW_)         // per-nc stride
#define V_   (NC_ * CST_)       // per-output-tensor elements

__device__ __forceinline__ float4 ld4z(const float* p, bool ok) {
    if (ok) return __ldcs(reinterpret_cast<const float4*>(p));
    return make_float4(0.f, 0.f, 0.f, 0.f);
}

__global__ __launch_bounds__(256, 4)
void sobel3d_kernel(const float* __restrict__ in, float* __restrict__ out) {
    const int lane = threadIdx.x;                    // 0..31
    const int y    = blockIdx.x * YT_ + threadIdx.y; // 0..127
    const int nc   = blockIdx.y;                     // 0..31
    const int x4   = lane * 4;

    const float* src = in + nc * CST_;
    float* gx = out;
    float* gy = out + V_;
    float* gz = out + 2 * V_;

    const bool ym_ok = (y > 0);
    const bool yp_ok = (y < H_ - 1);
    const int rm_off = (y - 1) * W_ + x4;
    const int r0_off = y * W_ + x4;
    const int rp_off = (y + 1) * W_ + x4;
    const int obase  = nc * CST_ + y * W_ + x4;

    // z rings of per-plane y-convolutions: s = smooth_y, d = deriv_y
    float4 zz = make_float4(0.f, 0.f, 0.f, 0.f);
    float4 s_m = zz, s_0 = zz, d_m = zz, d_0 = zz;

    // prefetch plane 0
    float4 f_m = ld4z(src + rm_off, ym_ok);
    float4 f_0 = __ldcs(reinterpret_cast<const float4*>(src + r0_off));
    float4 f_p = ld4z(src + rp_off, yp_ok);

    #pragma unroll 3
    for (int pz = 0; pz <= D_; ++pz) {
        // consume prefetched plane into s/d (frees f_* immediately)
        float4 s_p, d_p;
        d_p.x = f_p.x - f_m.x; d_p.y = f_p.y - f_m.y;
        d_p.z = f_p.z - f_m.z; d_p.w = f_p.w - f_m.w;
        s_p.x = f_m.x + 2.f * f_0.x + f_p.x;
        s_p.y = f_m.y + 2.f * f_0.y + f_p.y;
        s_p.z = f_m.z + 2.f * f_0.z + f_p.z;
        s_p.w = f_m.w + 2.f * f_0.w + f_p.w;

        // issue next plane's loads before the shuffle/store chain
        if (pz < D_) {
            const bool zin = (pz + 1) < D_;
            const float* pl = src + (pz + 1) * HW_;
            f_m = ld4z(pl + rm_off, zin && ym_ok);
            f_0 = ld4z(pl + r0_off, zin);
            f_p = ld4z(pl + rp_off, zin && yp_ok);
        }

        if (pz >= 1) {
            // z-combine first, then x-convolve the combined values
            float4 Sz, Dz, Zc;
            Sz.x = s_m.x + 2.f * s_0.x + s_p.x;
            Sz.y = s_m.y + 2.f * s_0.y + s_p.y;
            Sz.z = s_m.z + 2.f * s_0.z + s_p.z;
            Sz.w = s_m.w + 2.f * s_0.w + s_p.w;
            Dz.x = d_m.x + 2.f * d_0.x + d_p.x;
            Dz.y = d_m.y + 2.f * d_0.y + d_p.y;
            Dz.z = d_m.z + 2.f * d_0.z + d_p.z;
            Dz.w = d_m.w + 2.f * d_0.w + d_p.w;
            Zc.x = s_p.x - s_m.x; Zc.y = s_p.y - s_m.y;
            Zc.z = s_p.z - s_m.z; Zc.w = s_p.w - s_m.w;

            float SzL = __shfl_up_sync(0xffffffffu, Sz.w, 1);
            float SzR = __shfl_down_sync(0xffffffffu, Sz.x, 1);
            float DzL = __shfl_up_sync(0xffffffffu, Dz.w, 1);
            float DzR = __shfl_down_sync(0xffffffffu, Dz.x, 1);
            float ZcL = __shfl_up_sync(0xffffffffu, Zc.w, 1);
            float ZcR = __shfl_down_sync(0xffffffffu, Zc.x, 1);
            if (lane == 0)  { SzL = 0.f; DzL = 0.f; ZcL = 0.f; }
            if (lane == 31) { SzR = 0.f; DzR = 0.f; ZcR = 0.f; }

            float4 vx, vy, vz;
            vx.x = Sz.y - SzL;  vx.y = Sz.z - Sz.x;
            vx.z = Sz.w - Sz.y; vx.w = SzR  - Sz.z;
            vy.x = DzL  + 2.f * Dz.x + Dz.y;
            vy.y = Dz.x + 2.f * Dz.y + Dz.z;
            vy.z = Dz.y + 2.f * Dz.z + Dz.w;
            vy.w = Dz.z + 2.f * Dz.w + DzR;
            vz.x = ZcL  + 2.f * Zc.x + Zc.y;
            vz.y = Zc.x + 2.f * Zc.y + Zc.z;
            vz.z = Zc.y + 2.f * Zc.z + Zc.w;
            vz.w = Zc.z + 2.f * Zc.w + ZcR;

            const int o = obase + (pz - 1) * HW_;
            __stcs(reinterpret_cast<float4*>(gx + o), vx);
            __stcs(reinterpret_cast<float4*>(gy + o), vy);
            __stcs(reinterpret_cast<float4*>(gz + o), vz);
        }
        s_m = s_0; s_0 = s_p;
        d_m = d_0; d_0 = d_p;
    }
}

extern "C" void kernel_launch(void* const* d_in, const int* in_sizes, int n_in,
                              void* d_out, int out_size) {
    const float* x = (const float*)d_in[0];
    float* out = (float*)d_out;

    dim3 block(32, YT_, 1);            // 256 threads
    dim3 grid(H_ / YT_, NC_, 1);       // 512 blocks, one wave
    sobel3d_kernel<<<grid, block>>>(x, out);
}